// round 6
// baseline (speedup 1.0000x reference)
#include <cuda_runtime.h>
#include <cuda_fp16.h>
#include <cstdint>

#define NN 100000
#define EE 1600000
#define DD 64

// ---------------- scratch (device globals; no runtime allocation) ----------------
__device__ __align__(256) __half g_h16a [NN * DD];
__device__ __align__(256) __half g_h16b [NN * DD];
__device__ int   g_cnt[NN];
__device__ int   g_rowptr[NN];
__device__ int   g_cursor[NN];
__device__ int   g_col[EE];
__device__ float g_deginv[NN];
__device__ int   g_blksum[128];
__device__ float g_t4[NN];
__device__ float g_u4[NN];
__device__ int   g_is64;

// ---------------- helpers ----------------
__device__ __forceinline__ uint32_t smem_u32(const void* p) {
    uint32_t a;
    asm("{ .reg .u64 t; cvta.to.shared.u64 t, %1; cvt.u32.u64 %0, t; }" : "=r"(a) : "l"(p));
    return a;
}
__device__ __forceinline__ long long edge_at(const void* ei, long long idx, int is64) {
    if (is64) return ((const long long*)ei)[idx];
    return (long long)((const int*)ei)[idx];
}
__device__ __forceinline__ void ldsm_x4(uint32_t& r0, uint32_t& r1, uint32_t& r2,
                                        uint32_t& r3, uint32_t addr) {
    asm volatile("ldmatrix.sync.aligned.m8n8.x4.shared.b16 {%0,%1,%2,%3}, [%4];"
                 : "=r"(r0), "=r"(r1), "=r"(r2), "=r"(r3) : "r"(addr));
}
__device__ __forceinline__ void ldsm_x4_t(uint32_t& r0, uint32_t& r1, uint32_t& r2,
                                          uint32_t& r3, uint32_t addr) {
    asm volatile("ldmatrix.sync.aligned.m8n8.x4.trans.shared.b16 {%0,%1,%2,%3}, [%4];"
                 : "=r"(r0), "=r"(r1), "=r"(r2), "=r"(r3) : "r"(addr));
}
__device__ __forceinline__ void mma16816(float* d, uint32_t a0, uint32_t a1, uint32_t a2,
                                         uint32_t a3, uint32_t b0, uint32_t b1) {
    asm volatile(
        "mma.sync.aligned.m16n8k16.row.col.f32.f16.f16.f32 "
        "{%0,%1,%2,%3}, {%4,%5,%6,%7}, {%8,%9}, {%0,%1,%2,%3};"
        : "+f"(d[0]), "+f"(d[1]), "+f"(d[2]), "+f"(d[3])
        : "r"(a0), "r"(a1), "r"(a2), "r"(a3), "r"(b0), "r"(b1));
}
__device__ __forceinline__ int warp_iscan(int v, int lane) {
#pragma unroll
    for (int off = 1; off < 32; off <<= 1) {
        int t = __shfl_up_sync(0xffffffffu, v, off);
        if (lane >= off) v += t;
    }
    return v;
}

// ---------------- dtype detection: int64 vs int32 edge_index ----------------
__global__ void k_detect(const void* ei) {
    const unsigned* w = (const unsigned*)ei;
    int lane = threadIdx.x;
    bool allz = true;
    for (int i = lane; i < 1024; i += 32) allz &= (w[2 * i + 1] == 0u);
    allz = __all_sync(0xffffffffu, allz);
    if (lane == 0) g_is64 = allz ? 1 : 0;
}

// ---------------- x -> fp16 ----------------
__global__ void k_conv(const float* __restrict__ x, __half* __restrict__ o) {
    int i = blockIdx.x * 256 + threadIdx.x;
    if (i >= NN * DD / 4) return;
    float4 v = ((const float4*)x)[i];
    ((__half2*)o)[2 * i]     = __floats2half2_rn(v.x, v.y);
    ((__half2*)o)[2 * i + 1] = __floats2half2_rn(v.z, v.w);
}

// ---------------- CSR build ----------------
__global__ void k_hist(const void* ei) {
    int e = blockIdx.x * 256 + threadIdx.x;
    int is64 = g_is64;
    int d = (int)edge_at(ei, (long long)EE + e, is64);
    atomicAdd(&g_cnt[d], 1);
}

// 1024-thread shuffle scan, 2 barriers
__global__ void k_scan_partial() {
    __shared__ int wsum[32];
    int i = blockIdx.x * 1024 + threadIdx.x;
    int lane = threadIdx.x & 31, w = threadIdx.x >> 5;
    int v = (i < NN) ? g_cnt[i] : 0;
    int s = warp_iscan(v, lane);
    if (lane == 31) wsum[w] = s;
    __syncthreads();
    if (w == 0) wsum[lane] = warp_iscan(wsum[lane], lane);
    __syncthreads();
    int incl = s + ((w > 0) ? wsum[w - 1] : 0);
    if (i < NN) g_rowptr[i] = incl - v;
    if (threadIdx.x == 1023) g_blksum[blockIdx.x] = incl;
}

__global__ void k_scan_blk(int nb) {
    __shared__ int wsum[4];
    int t = threadIdx.x, lane = t & 31, w = t >> 5;
    int v = (t < nb) ? g_blksum[t] : 0;
    int s = warp_iscan(v, lane);
    if (lane == 31) wsum[w] = s;
    __syncthreads();
    if (t == 0) {
        int run = 0;
        for (int q = 0; q < 4; q++) { int x = wsum[q]; wsum[q] = run; run += x; }
    }
    __syncthreads();
    if (t < nb) g_blksum[t] = s - v + wsum[w];
}

__global__ void k_scan_add() {
    int i = blockIdx.x * 1024 + threadIdx.x;
    if (i < NN) {
        int r = g_rowptr[i] + g_blksum[blockIdx.x];
        g_rowptr[i] = r;
        g_cursor[i] = r;
        int c = g_cnt[i];
        g_deginv[i] = 1.0f / (float)(c > 0 ? c : 1);
    }
}

__global__ void k_fill(const void* ei) {
    int e = blockIdx.x * 256 + threadIdx.x;
    int is64 = g_is64;
    int dn = (int)edge_at(ei, (long long)EE + e, is64);
    int sn = (int)edge_at(ei, (long long)e, is64);
    int pos = atomicAdd(&g_cursor[dn], 1);
    g_col[pos] = sn;
}

// ---------------- fused layer: gather-agg (into smem) + HMMA GEMM + bias + relu ------
// block = 256 thr / 8 warps; tile = 128 nodes. X tile [128][136 halves]:
// cols 0-63 = h (staged), cols 64-127 = mean-aggregated neighbors (gathered here).
#define XS 136
#define WS2 72
#define OFF_WS (128 * XS)                 // halves
#define OFF_WN (OFF_WS + 64 * WS2)
#define OFF_BIAS_B ((OFF_WN + 64 * WS2) * 2)  // bytes
#define SMEM_HM (OFF_BIAS_B + 64 * 4)

__global__ __launch_bounds__(256) void k_layer(
    const __half* __restrict__ h16,
    const float* __restrict__ Ws, const float* __restrict__ Wn,
    const float* __restrict__ bias, __half* __restrict__ out16) {
    extern __shared__ char smem[];
    __half* sx = (__half*)smem;
    float* sbias = (float*)(smem + OFF_BIAS_B);
    uint32_t sb = smem_u32(smem);

    int tid = threadIdx.x, wid = tid >> 5, lane = tid & 31;
    int base = blockIdx.x * 128;

    // stage weights (fp32 -> fp16) + bias
    for (int idx = tid; idx < 4096; idx += 256) {
        int k = idx >> 6, n = idx & 63;
        sx[OFF_WS + k * WS2 + n] = __float2half_rn(Ws[idx]);
        sx[OFF_WN + k * WS2 + n] = __float2half_rn(Wn[idx]);
    }
    if (tid < 64) sbias[tid] = bias[tid];

    // stage h rows (X cols 0-63)
    for (int idx = tid; idx < 128 * 8; idx += 256) {
        int r = idx >> 3, q = idx & 7;
        int node = base + r;
        uint4 v = make_uint4(0u, 0u, 0u, 0u);
        if (node < NN) v = *(const uint4*)(h16 + (size_t)node * DD + q * 8);
        *(uint4*)((char*)smem + (size_t)r * (XS * 2) + q * 16) = v;
    }

    // gather-aggregate into X cols 64-127 (warp per node, 16 nodes/warp)
    {
        int g = lane >> 3, fl = lane & 7;
        for (int n = wid; n < 128; n += 8) {
            int node = base + n;
            if (node >= NN) break;
            int start = g_rowptr[node];
            int cnt   = g_cnt[node];
            const int* __restrict__ col = g_col + start;

            float acc[8];
#pragma unroll
            for (int q = 0; q < 8; q++) acc[q] = 0.f;

            const uint4 z4 = make_uint4(0u, 0u, 0u, 0u);
            for (int j = 4 * g; j < cnt; j += 16) {
                uint4 v0 = *(const uint4*)(h16 + (size_t)col[j] * DD + fl * 8);
                uint4 v1 = (j + 1 < cnt) ? *(const uint4*)(h16 + (size_t)col[j + 1] * DD + fl * 8) : z4;
                uint4 v2 = (j + 2 < cnt) ? *(const uint4*)(h16 + (size_t)col[j + 2] * DD + fl * 8) : z4;
                uint4 v3 = (j + 3 < cnt) ? *(const uint4*)(h16 + (size_t)col[j + 3] * DD + fl * 8) : z4;
                const __half2* a0 = (const __half2*)&v0;
                const __half2* a1 = (const __half2*)&v1;
                const __half2* a2 = (const __half2*)&v2;
                const __half2* a3 = (const __half2*)&v3;
#pragma unroll
                for (int q = 0; q < 4; q++) {
                    __half2 s = __hadd2(__hadd2(a0[q], a1[q]), __hadd2(a2[q], a3[q]));
                    float2 f = __half22float2(s);
                    acc[2 * q]     += f.x;
                    acc[2 * q + 1] += f.y;
                }
            }
#pragma unroll
            for (int q = 0; q < 8; q++) {
                acc[q] += __shfl_xor_sync(0xffffffffu, acc[q], 8);
                acc[q] += __shfl_xor_sync(0xffffffffu, acc[q], 16);
            }
            if (g == 0) {
                float di = g_deginv[node];
                __half2 o[4];
#pragma unroll
                for (int q = 0; q < 4; q++)
                    o[q] = __floats2half2_rn(acc[2 * q] * di, acc[2 * q + 1] * di);
                *(uint4*)((char*)smem + (size_t)n * (XS * 2) + 128 + fl * 16) = *(uint4*)o;
            }
        }
    }
    __syncthreads();

    // HMMA: [128x128] X @ [128x64] [Ws;Wn]
    float acc[8][4];
#pragma unroll
    for (int nt = 0; nt < 8; nt++)
#pragma unroll
        for (int q = 0; q < 4; q++) acc[nt][q] = 0.f;

    int arow = wid * 16 + (lane & 15);
    int acolq = (lane >> 4) << 3;

#pragma unroll
    for (int ks = 0; ks < 8; ks++) {
        uint32_t a0, a1, a2, a3;
        ldsm_x4(a0, a1, a2, a3, sb + (arow * XS + ks * 16 + acolq) * 2);
        uint32_t wbase = (ks < 4) ? OFF_WS : OFF_WN;
        int kl = (ks & 3) * 16 + (lane & 15);
#pragma unroll
        for (int np = 0; np < 4; np++) {
            uint32_t b0, b1, b2, b3;
            ldsm_x4_t(b0, b1, b2, b3, sb + (wbase + kl * WS2 + np * 16 + acolq) * 2);
            mma16816(acc[np * 2],     a0, a1, a2, a3, b0, b1);
            mma16816(acc[np * 2 + 1], a0, a1, a2, a3, b2, b3);
        }
    }

    // epilogue: bias + relu -> fp16
    int r0 = base + wid * 16 + (lane >> 2);
    int r1 = r0 + 8;
    int cb = (lane & 3) * 2;
#pragma unroll
    for (int nt = 0; nt < 8; nt++) {
        int c = nt * 8 + cb;
        float bb0 = sbias[c], bb1 = sbias[c + 1];
        if (r0 < NN) {
            float v0 = fmaxf(acc[nt][0] + bb0, 0.f);
            float v1 = fmaxf(acc[nt][1] + bb1, 0.f);
            *(__half2*)(out16 + (size_t)r0 * DD + c) = __floats2half2_rn(v0, v1);
        }
        if (r1 < NN) {
            float v0 = fmaxf(acc[nt][2] + bb0, 0.f);
            float v1 = fmaxf(acc[nt][3] + bb1, 0.f);
            *(__half2*)(out16 + (size_t)r1 * DD + c) = __floats2half2_rn(v0, v1);
        }
    }
}

// ---------------- layer 4 ----------------
__global__ void k_lin4(const __half* __restrict__ h, const float* __restrict__ ws,
                       const float* __restrict__ wn, const float* __restrict__ b) {
    __shared__ float sws[64], swn[64];
    int t = threadIdx.x;
    if (t < 64) { sws[t] = ws[t]; swn[t] = wn[t]; }
    __syncthreads();
    int node = blockIdx.x * 8 + (t >> 5);
    if (node >= NN) return;
    int lane = t & 31;
    float2 f = __half22float2(((const __half2*)(h + (size_t)node * DD))[lane]);
    float u  = f.x * sws[2 * lane] + f.y * sws[2 * lane + 1];
    float tt = f.x * swn[2 * lane] + f.y * swn[2 * lane + 1];
#pragma unroll
    for (int o = 16; o; o >>= 1) {
        u  += __shfl_down_sync(0xffffffffu, u, o);
        tt += __shfl_down_sync(0xffffffffu, tt, o);
    }
    if (lane == 0) { g_u4[node] = u + b[0]; g_t4[node] = tt; }
}

__global__ void k_out4(float* __restrict__ out) {
    int node = blockIdx.x * 8 + (threadIdx.x >> 5);
    if (node >= NN) return;
    int lane = threadIdx.x & 31;
    int start = g_rowptr[node];
    int cnt   = g_cnt[node];
    float acc = 0.f;
    for (int j = lane; j < cnt; j += 32) acc += g_t4[g_col[start + j]];
#pragma unroll
    for (int o = 16; o; o >>= 1) acc += __shfl_down_sync(0xffffffffu, acc, o);
    if (lane == 0) {
        float z = g_u4[node] + g_deginv[node] * acc;
        out[node] = 1.0f / (1.0f + expf(-z));
    }
}

// ---------------- launch ----------------
extern "C" void kernel_launch(void* const* d_in, const int* in_sizes, int n_in,
                              void* d_out, int out_size) {
    const float* x   = (const float*)d_in[0];
    const void*  ei  = d_in[1];
    const float* Ws1 = (const float*)d_in[2];
    const float* Wn1 = (const float*)d_in[3];
    const float* b1  = (const float*)d_in[4];
    const float* Ws2 = (const float*)d_in[5];
    const float* Wn2 = (const float*)d_in[6];
    const float* b2  = (const float*)d_in[7];
    const float* Ws3 = (const float*)d_in[8];
    const float* Wn3 = (const float*)d_in[9];
    const float* b3  = (const float*)d_in[10];
    const float* Ws4 = (const float*)d_in[11];
    const float* Wn4 = (const float*)d_in[12];
    const float* b4  = (const float*)d_in[13];
    float* out = (float*)d_out;

    static __half *pHa = nullptr, *pHb = nullptr;
    static int* pcnt = nullptr;
    if (!pcnt) {
        void* p;
        cudaGetSymbolAddress(&p, g_cnt);    pcnt = (int*)p;
        cudaGetSymbolAddress(&p, g_h16a);   pHa = (__half*)p;
        cudaGetSymbolAddress(&p, g_h16b);   pHb = (__half*)p;
        cudaFuncSetAttribute(k_layer, cudaFuncAttributeMaxDynamicSharedMemorySize,
                             SMEM_HM);
    }

    const int nbScan = (NN + 1023) / 1024;
    const int gridE  = EE / 256;
    const int gridN8 = (NN + 7) / 8;
    const int gridG  = (NN + 127) / 128;
    const int gridC  = (NN * DD / 4 + 255) / 256;

    // CSR build + x conversion
    k_detect<<<1, 32>>>(ei);
    cudaMemsetAsync(pcnt, 0, NN * sizeof(int));
    k_conv<<<gridC, 256>>>(x, pHa);
    k_hist<<<gridE, 256>>>(ei);
    k_scan_partial<<<nbScan, 1024>>>();
    k_scan_blk<<<1, 128>>>(nbScan);
    k_scan_add<<<nbScan, 1024>>>();
    k_fill<<<gridE, 256>>>(ei);

    // layers 1-3 (fused gather + GEMM)
    k_layer<<<gridG, 256, SMEM_HM>>>(pHa, Ws1, Wn1, b1, pHb);
    k_layer<<<gridG, 256, SMEM_HM>>>(pHb, Ws2, Wn2, b2, pHa);
    k_layer<<<gridG, 256, SMEM_HM>>>(pHa, Ws3, Wn3, b3, pHb);
    // layer 4 (transform-first, scalar aggregation)
    k_lin4<<<gridN8, 256>>>(pHb, Ws4, Wn4, b4);
    k_out4<<<gridN8, 256>>>(out);
}

// round 7
// speedup vs baseline: 1.0114x; 1.0114x over previous
#include <cuda_runtime.h>
#include <cuda_fp16.h>
#include <cstdint>

#define NN 100000
#define EE 1600000
#define DD 64

// ---------------- scratch (device globals; no runtime allocation) ----------------
__device__ __align__(256) __half g_h16a [NN * DD];
__device__ __align__(256) __half g_h16b [NN * DD];
__device__ __align__(256) __half g_agg16[NN * DD];
__device__ int   g_cnt[NN];
__device__ int   g_rowptr[NN];
__device__ int   g_cursor[NN];
__device__ int   g_col[EE];
__device__ float g_deginv[NN];
__device__ int   g_blksum[128];
__device__ float g_t4[NN];
__device__ float g_u4[NN];
__device__ int   g_is64;

// ---------------- helpers ----------------
__device__ __forceinline__ uint32_t smem_u32(const void* p) {
    uint32_t a;
    asm("{ .reg .u64 t; cvta.to.shared.u64 t, %1; cvt.u32.u64 %0, t; }" : "=r"(a) : "l"(p));
    return a;
}
__device__ __forceinline__ long long edge_at(const void* ei, long long idx, int is64) {
    if (is64) return ((const long long*)ei)[idx];
    return (long long)((const int*)ei)[idx];
}
__device__ __forceinline__ void ldsm_x4(uint32_t& r0, uint32_t& r1, uint32_t& r2,
                                        uint32_t& r3, uint32_t addr) {
    asm volatile("ldmatrix.sync.aligned.m8n8.x4.shared.b16 {%0,%1,%2,%3}, [%4];"
                 : "=r"(r0), "=r"(r1), "=r"(r2), "=r"(r3) : "r"(addr));
}
__device__ __forceinline__ void ldsm_x4_t(uint32_t& r0, uint32_t& r1, uint32_t& r2,
                                          uint32_t& r3, uint32_t addr) {
    asm volatile("ldmatrix.sync.aligned.m8n8.x4.trans.shared.b16 {%0,%1,%2,%3}, [%4];"
                 : "=r"(r0), "=r"(r1), "=r"(r2), "=r"(r3) : "r"(addr));
}
__device__ __forceinline__ void mma16816(float* d, uint32_t a0, uint32_t a1, uint32_t a2,
                                         uint32_t a3, uint32_t b0, uint32_t b1) {
    asm volatile(
        "mma.sync.aligned.m16n8k16.row.col.f32.f16.f16.f32 "
        "{%0,%1,%2,%3}, {%4,%5,%6,%7}, {%8,%9}, {%0,%1,%2,%3};"
        : "+f"(d[0]), "+f"(d[1]), "+f"(d[2]), "+f"(d[3])
        : "r"(a0), "r"(a1), "r"(a2), "r"(a3), "r"(b0), "r"(b1));
}
__device__ __forceinline__ int warp_iscan(int v, int lane) {
#pragma unroll
    for (int off = 1; off < 32; off <<= 1) {
        int t = __shfl_up_sync(0xffffffffu, v, off);
        if (lane >= off) v += t;
    }
    return v;
}

// ---------------- dtype detection: int64 vs int32 edge_index ----------------
__global__ void k_detect(const void* ei) {
    const unsigned* w = (const unsigned*)ei;
    int lane = threadIdx.x;
    bool allz = true;
    for (int i = lane; i < 1024; i += 32) allz &= (w[2 * i + 1] == 0u);
    allz = __all_sync(0xffffffffu, allz);
    if (lane == 0) g_is64 = allz ? 1 : 0;
}

// ---------------- x -> fp16 ----------------
__global__ void k_conv(const float* __restrict__ x, __half* __restrict__ o) {
    int i = blockIdx.x * 256 + threadIdx.x;
    if (i >= NN * DD / 4) return;
    float4 v = ((const float4*)x)[i];
    ((__half2*)o)[2 * i]     = __floats2half2_rn(v.x, v.y);
    ((__half2*)o)[2 * i + 1] = __floats2half2_rn(v.z, v.w);
}

// ---------------- CSR build ----------------
__global__ void k_hist(const void* ei) {
    int e = blockIdx.x * 256 + threadIdx.x;
    int is64 = g_is64;
    int d = (int)edge_at(ei, (long long)EE + e, is64);
    atomicAdd(&g_cnt[d], 1);
}

// 1024-thread shuffle scan, 2 barriers
__global__ void k_scan_partial() {
    __shared__ int wsum[32];
    int i = blockIdx.x * 1024 + threadIdx.x;
    int lane = threadIdx.x & 31, w = threadIdx.x >> 5;
    int v = (i < NN) ? g_cnt[i] : 0;
    int s = warp_iscan(v, lane);
    if (lane == 31) wsum[w] = s;
    __syncthreads();
    if (w == 0) wsum[lane] = warp_iscan(wsum[lane], lane);
    __syncthreads();
    int incl = s + ((w > 0) ? wsum[w - 1] : 0);
    if (i < NN) g_rowptr[i] = incl - v;
    if (threadIdx.x == 1023) g_blksum[blockIdx.x] = incl;
}

__global__ void k_scan_blk(int nb) {
    __shared__ int wsum[4];
    int t = threadIdx.x, lane = t & 31, w = t >> 5;
    int v = (t < nb) ? g_blksum[t] : 0;
    int s = warp_iscan(v, lane);
    if (lane == 31) wsum[w] = s;
    __syncthreads();
    if (t == 0) {
        int run = 0;
        for (int q = 0; q < 4; q++) { int x = wsum[q]; wsum[q] = run; run += x; }
    }
    __syncthreads();
    if (t < nb) g_blksum[t] = s - v + wsum[w];
}

__global__ void k_scan_add() {
    int i = blockIdx.x * 1024 + threadIdx.x;
    if (i < NN) {
        int r = g_rowptr[i] + g_blksum[blockIdx.x];
        g_rowptr[i] = r;
        g_cursor[i] = r;
        int c = g_cnt[i];
        g_deginv[i] = 1.0f / (float)(c > 0 ? c : 1);
    }
}

__global__ void k_fill(const void* ei) {
    int e = blockIdx.x * 256 + threadIdx.x;
    int is64 = g_is64;
    int dn = (int)edge_at(ei, (long long)EE + e, is64);
    int sn = (int)edge_at(ei, (long long)e, is64);
    int pos = atomicAdd(&g_cursor[dn], 1);
    g_col[pos] = sn;
}

// ---------------- aggregation: fp16 gather, 4-way HADD2 tree, fp32 accumulate --------
// warp per node; 4 groups of 8 lanes; each group sums 4 neighbor rows per iter.
__global__ __launch_bounds__(256) void k_agg16(const __half* __restrict__ h,
                                               __half* __restrict__ a) {
    int node = blockIdx.x * 8 + (threadIdx.x >> 5);
    if (node >= NN) return;
    int lane = threadIdx.x & 31;
    int g  = lane >> 3;
    int fl = lane & 7;
    int start = g_rowptr[node];
    int cnt   = g_cnt[node];
    const int* __restrict__ col = g_col + start;

    float acc[8];
#pragma unroll
    for (int q = 0; q < 8; q++) acc[q] = 0.f;

    const uint4 z4 = make_uint4(0u, 0u, 0u, 0u);
    for (int j = 4 * g; j < cnt; j += 16) {
        uint4 v0 = *(const uint4*)(h + (size_t)col[j] * DD + fl * 8);
        uint4 v1 = (j + 1 < cnt) ? *(const uint4*)(h + (size_t)col[j + 1] * DD + fl * 8) : z4;
        uint4 v2 = (j + 2 < cnt) ? *(const uint4*)(h + (size_t)col[j + 2] * DD + fl * 8) : z4;
        uint4 v3 = (j + 3 < cnt) ? *(const uint4*)(h + (size_t)col[j + 3] * DD + fl * 8) : z4;
        const __half2* a0 = (const __half2*)&v0;
        const __half2* a1 = (const __half2*)&v1;
        const __half2* a2 = (const __half2*)&v2;
        const __half2* a3 = (const __half2*)&v3;
#pragma unroll
        for (int q = 0; q < 4; q++) {
            __half2 s = __hadd2(__hadd2(a0[q], a1[q]), __hadd2(a2[q], a3[q]));
            float2 f = __half22float2(s);
            acc[2 * q]     += f.x;
            acc[2 * q + 1] += f.y;
        }
    }
#pragma unroll
    for (int q = 0; q < 8; q++) {
        acc[q] += __shfl_xor_sync(0xffffffffu, acc[q], 8);
        acc[q] += __shfl_xor_sync(0xffffffffu, acc[q], 16);
    }
    if (g == 0) {
        float di = g_deginv[node];
        __half2 o[4];
#pragma unroll
        for (int q = 0; q < 4; q++)
            o[q] = __floats2half2_rn(acc[2 * q] * di, acc[2 * q + 1] * di);
        *(uint4*)(a + (size_t)node * DD + fl * 8) = *(uint4*)o;
    }
}

// ---------------- HMMA fused GEMM: out16 = relu([h|a] @ [Ws;Wn] + b) ----------------
#define XS 136
#define WS2 72
#define OFF_WS (128 * XS)                 // halves
#define OFF_WN (OFF_WS + 64 * WS2)
#define OFF_BIAS_B ((OFF_WN + 64 * WS2) * 2)  // bytes
#define SMEM_HM (OFF_BIAS_B + 64 * 4)

__global__ __launch_bounds__(256) void k_gemm_hmma(
    const __half* __restrict__ h16, const __half* __restrict__ a16,
    const float* __restrict__ Ws, const float* __restrict__ Wn,
    const float* __restrict__ bias, __half* __restrict__ out16) {
    extern __shared__ char smem[];
    __half* sx = (__half*)smem;
    float* sbias = (float*)(smem + OFF_BIAS_B);
    uint32_t sb = smem_u32(smem);

    int tid = threadIdx.x, wid = tid >> 5, lane = tid & 31;
    int base = blockIdx.x * 128;

    for (int idx = tid; idx < 4096; idx += 256) {
        int k = idx >> 6, n = idx & 63;
        sx[OFF_WS + k * WS2 + n] = __float2half_rn(Ws[idx]);
        sx[OFF_WN + k * WS2 + n] = __float2half_rn(Wn[idx]);
    }
    if (tid < 64) sbias[tid] = bias[tid];

    for (int idx = tid; idx < 128 * 16; idx += 256) {
        int r = idx >> 4, q = idx & 15;
        int node = base + r;
        uint4 v = make_uint4(0u, 0u, 0u, 0u);
        if (node < NN) {
            const __half* src = (q < 8) ? (h16 + (size_t)node * DD + q * 8)
                                        : (a16 + (size_t)node * DD + (q - 8) * 8);
            v = *(const uint4*)src;
        }
        *(uint4*)((char*)smem + (size_t)r * (XS * 2) + q * 16) = v;
    }
    __syncthreads();

    float acc[8][4];
#pragma unroll
    for (int nt = 0; nt < 8; nt++)
#pragma unroll
        for (int q = 0; q < 4; q++) acc[nt][q] = 0.f;

    int arow = wid * 16 + (lane & 15);
    int acolq = (lane >> 4) << 3;

#pragma unroll
    for (int ks = 0; ks < 8; ks++) {
        uint32_t a0, a1, a2, a3;
        ldsm_x4(a0, a1, a2, a3, sb + (arow * XS + ks * 16 + acolq) * 2);
        uint32_t wbase = (ks < 4) ? OFF_WS : OFF_WN;
        int kl = (ks & 3) * 16 + (lane & 15);
#pragma unroll
        for (int np = 0; np < 4; np++) {
            uint32_t b0, b1, b2, b3;
            ldsm_x4_t(b0, b1, b2, b3, sb + (wbase + kl * WS2 + np * 16 + acolq) * 2);
            mma16816(acc[np * 2],     a0, a1, a2, a3, b0, b1);
            mma16816(acc[np * 2 + 1], a0, a1, a2, a3, b2, b3);
        }
    }

    int r0 = base + wid * 16 + (lane >> 2);
    int r1 = r0 + 8;
    int cb = (lane & 3) * 2;
#pragma unroll
    for (int nt = 0; nt < 8; nt++) {
        int c = nt * 8 + cb;
        float bb0 = sbias[c], bb1 = sbias[c + 1];
        if (r0 < NN) {
            float v0 = fmaxf(acc[nt][0] + bb0, 0.f);
            float v1 = fmaxf(acc[nt][1] + bb1, 0.f);
            *(__half2*)(out16 + (size_t)r0 * DD + c) = __floats2half2_rn(v0, v1);
        }
        if (r1 < NN) {
            float v0 = fmaxf(acc[nt][2] + bb0, 0.f);
            float v1 = fmaxf(acc[nt][3] + bb1, 0.f);
            *(__half2*)(out16 + (size_t)r1 * DD + c) = __floats2half2_rn(v0, v1);
        }
    }
}

// ---------------- layer 4 ----------------
__global__ void k_lin4(const __half* __restrict__ h, const float* __restrict__ ws,
                       const float* __restrict__ wn, const float* __restrict__ b) {
    __shared__ float sws[64], swn[64];
    int t = threadIdx.x;
    if (t < 64) { sws[t] = ws[t]; swn[t] = wn[t]; }
    __syncthreads();
    int node = blockIdx.x * 8 + (t >> 5);
    if (node >= NN) return;
    int lane = t & 31;
    float2 f = __half22float2(((const __half2*)(h + (size_t)node * DD))[lane]);
    float u  = f.x * sws[2 * lane] + f.y * sws[2 * lane + 1];
    float tt = f.x * swn[2 * lane] + f.y * swn[2 * lane + 1];
#pragma unroll
    for (int o = 16; o; o >>= 1) {
        u  += __shfl_down_sync(0xffffffffu, u, o);
        tt += __shfl_down_sync(0xffffffffu, tt, o);
    }
    if (lane == 0) { g_u4[node] = u + b[0]; g_t4[node] = tt; }
}

__global__ void k_out4(float* __restrict__ out) {
    int node = blockIdx.x * 8 + (threadIdx.x >> 5);
    if (node >= NN) return;
    int lane = threadIdx.x & 31;
    int start = g_rowptr[node];
    int cnt   = g_cnt[node];
    float acc = 0.f;
    for (int j = lane; j < cnt; j += 32) acc += g_t4[g_col[start + j]];
#pragma unroll
    for (int o = 16; o; o >>= 1) acc += __shfl_down_sync(0xffffffffu, acc, o);
    if (lane == 0) {
        float z = g_u4[node] + g_deginv[node] * acc;
        out[node] = 1.0f / (1.0f + expf(-z));
    }
}

// ---------------- launch ----------------
extern "C" void kernel_launch(void* const* d_in, const int* in_sizes, int n_in,
                              void* d_out, int out_size) {
    const float* x   = (const float*)d_in[0];
    const void*  ei  = d_in[1];
    const float* Ws1 = (const float*)d_in[2];
    const float* Wn1 = (const float*)d_in[3];
    const float* b1  = (const float*)d_in[4];
    const float* Ws2 = (const float*)d_in[5];
    const float* Wn2 = (const float*)d_in[6];
    const float* b2  = (const float*)d_in[7];
    const float* Ws3 = (const float*)d_in[8];
    const float* Wn3 = (const float*)d_in[9];
    const float* b3  = (const float*)d_in[10];
    const float* Ws4 = (const float*)d_in[11];
    const float* Wn4 = (const float*)d_in[12];
    const float* b4  = (const float*)d_in[13];
    float* out = (float*)d_out;

    static __half *pHa = nullptr, *pHb = nullptr, *pAg = nullptr;
    static int* pcnt = nullptr;
    if (!pcnt) {
        void* p;
        cudaGetSymbolAddress(&p, g_cnt);    pcnt = (int*)p;
        cudaGetSymbolAddress(&p, g_h16a);   pHa = (__half*)p;
        cudaGetSymbolAddress(&p, g_h16b);   pHb = (__half*)p;
        cudaGetSymbolAddress(&p, g_agg16);  pAg = (__half*)p;
        cudaFuncSetAttribute(k_gemm_hmma, cudaFuncAttributeMaxDynamicSharedMemorySize,
                             SMEM_HM);
    }

    const int nbScan = (NN + 1023) / 1024;
    const int gridE  = EE / 256;
    const int gridN8 = (NN + 7) / 8;
    const int gridG  = (NN + 127) / 128;
    const int gridC  = (NN * DD / 4 + 255) / 256;

    // CSR build + x conversion
    k_detect<<<1, 32>>>(ei);
    cudaMemsetAsync(pcnt, 0, NN * sizeof(int));
    k_conv<<<gridC, 256>>>(x, pHa);
    k_hist<<<gridE, 256>>>(ei);
    k_scan_partial<<<nbScan, 1024>>>();
    k_scan_blk<<<1, 128>>>(nbScan);
    k_scan_add<<<nbScan, 1024>>>();
    k_fill<<<gridE, 256>>>(ei);

    // layer 1
    k_agg16<<<gridN8, 256>>>(pHa, pAg);
    k_gemm_hmma<<<gridG, 256, SMEM_HM>>>(pHa, pAg, Ws1, Wn1, b1, pHb);
    // layer 2
    k_agg16<<<gridN8, 256>>>(pHb, pAg);
    k_gemm_hmma<<<gridG, 256, SMEM_HM>>>(pHb, pAg, Ws2, Wn2, b2, pHa);
    // layer 3
    k_agg16<<<gridN8, 256>>>(pHa, pAg);
    k_gemm_hmma<<<gridG, 256, SMEM_HM>>>(pHa, pAg, Ws3, Wn3, b3, pHb);
    // layer 4 (transform-first, scalar aggregation)
    k_lin4<<<gridN8, 256>>>(pHb, Ws4, Wn4, b4);
    k_out4<<<gridN8, 256>>>(out);
}

// round 8
// speedup vs baseline: 1.1376x; 1.1248x over previous
#include <cuda_runtime.h>
#include <cuda_fp16.h>
#include <cstdint>

#define NN 100000
#define EE 1600000
#define DD 64

// ---------------- scratch (device globals; no runtime allocation) ----------------
__device__ __align__(256) __half g_h16a [NN * DD];
__device__ __align__(256) __half g_h16b [NN * DD];
__device__ __align__(256) __half g_agg16[NN * DD];
__device__ int   g_cnt[NN];
__device__ int   g_rowptr[NN];
__device__ int   g_cursor[NN];
__device__ int   g_col[EE];
__device__ float g_deginv[NN];
__device__ int   g_blksum[128];
__device__ float g_t4[NN];
__device__ float g_u4[NN];
__device__ int   g_is64;

// ---------------- helpers ----------------
__device__ __forceinline__ uint32_t smem_u32(const void* p) {
    uint32_t a;
    asm("{ .reg .u64 t; cvta.to.shared.u64 t, %1; cvt.u32.u64 %0, t; }" : "=r"(a) : "l"(p));
    return a;
}
__device__ __forceinline__ long long edge_at(const void* ei, long long idx, int is64) {
    if (is64) return ((const long long*)ei)[idx];
    return (long long)((const int*)ei)[idx];
}
__device__ __forceinline__ void ldsm_x4(uint32_t& r0, uint32_t& r1, uint32_t& r2,
                                        uint32_t& r3, uint32_t addr) {
    asm volatile("ldmatrix.sync.aligned.m8n8.x4.shared.b16 {%0,%1,%2,%3}, [%4];"
                 : "=r"(r0), "=r"(r1), "=r"(r2), "=r"(r3) : "r"(addr));
}
__device__ __forceinline__ void ldsm_x4_t(uint32_t& r0, uint32_t& r1, uint32_t& r2,
                                          uint32_t& r3, uint32_t addr) {
    asm volatile("ldmatrix.sync.aligned.m8n8.x4.trans.shared.b16 {%0,%1,%2,%3}, [%4];"
                 : "=r"(r0), "=r"(r1), "=r"(r2), "=r"(r3) : "r"(addr));
}
__device__ __forceinline__ void mma16816(float* d, uint32_t a0, uint32_t a1, uint32_t a2,
                                         uint32_t a3, uint32_t b0, uint32_t b1) {
    asm volatile(
        "mma.sync.aligned.m16n8k16.row.col.f32.f16.f16.f32 "
        "{%0,%1,%2,%3}, {%4,%5,%6,%7}, {%8,%9}, {%0,%1,%2,%3};"
        : "+f"(d[0]), "+f"(d[1]), "+f"(d[2]), "+f"(d[3])
        : "r"(a0), "r"(a1), "r"(a2), "r"(a3), "r"(b0), "r"(b1));
}
__device__ __forceinline__ int warp_iscan(int v, int lane) {
#pragma unroll
    for (int off = 1; off < 32; off <<= 1) {
        int t = __shfl_up_sync(0xffffffffu, v, off);
        if (lane >= off) v += t;
    }
    return v;
}

// ---------------- pre: x -> fp16 conversion + zero g_cnt + dtype detect ----------------
__global__ void k_pre(const float* __restrict__ x, __half* __restrict__ o,
                      const void* ei) {
    int i = blockIdx.x * 256 + threadIdx.x;
    if (i < NN * DD / 4) {
        float4 v = ((const float4*)x)[i];
        ((__half2*)o)[2 * i]     = __floats2half2_rn(v.x, v.y);
        ((__half2*)o)[2 * i + 1] = __floats2half2_rn(v.z, v.w);
    }
    if (i < NN) g_cnt[i] = 0;
    if (blockIdx.x == 0 && threadIdx.x < 32) {
        const unsigned* w = (const unsigned*)ei;
        int lane = threadIdx.x;
        bool allz = true;
        for (int q = lane; q < 1024; q += 32) allz &= (w[2 * q + 1] == 0u);
        allz = __all_sync(0xffffffffu, allz);
        if (lane == 0) g_is64 = allz ? 1 : 0;
    }
}

// ---------------- CSR build ----------------
__global__ void k_hist(const void* ei) {
    int e = blockIdx.x * 256 + threadIdx.x;
    int is64 = g_is64;
    int d = (int)edge_at(ei, (long long)EE + e, is64);
    atomicAdd(&g_cnt[d], 1);
}

// 1024-thread shuffle scan, 2 barriers
__global__ void k_scan_partial() {
    __shared__ int wsum[32];
    int i = blockIdx.x * 1024 + threadIdx.x;
    int lane = threadIdx.x & 31, w = threadIdx.x >> 5;
    int v = (i < NN) ? g_cnt[i] : 0;
    int s = warp_iscan(v, lane);
    if (lane == 31) wsum[w] = s;
    __syncthreads();
    if (w == 0) wsum[lane] = warp_iscan(wsum[lane], lane);
    __syncthreads();
    int incl = s + ((w > 0) ? wsum[w - 1] : 0);
    if (i < NN) g_rowptr[i] = incl - v;
    if (threadIdx.x == 1023) g_blksum[blockIdx.x] = incl;
}

__global__ void k_scan_blk(int nb) {
    __shared__ int wsum[4];
    int t = threadIdx.x, lane = t & 31, w = t >> 5;
    int v = (t < nb) ? g_blksum[t] : 0;
    int s = warp_iscan(v, lane);
    if (lane == 31) wsum[w] = s;
    __syncthreads();
    if (t == 0) {
        int run = 0;
        for (int q = 0; q < 4; q++) { int x = wsum[q]; wsum[q] = run; run += x; }
    }
    __syncthreads();
    if (t < nb) g_blksum[t] = s - v + wsum[w];
}

__global__ void k_scan_add() {
    int i = blockIdx.x * 1024 + threadIdx.x;
    if (i < NN) {
        int r = g_rowptr[i] + g_blksum[blockIdx.x];
        g_rowptr[i] = r;
        g_cursor[i] = r;
        int c = g_cnt[i];
        g_deginv[i] = 1.0f / (float)(c > 0 ? c : 1);
    }
}

__global__ void k_fill(const void* ei) {
    int e = blockIdx.x * 256 + threadIdx.x;
    int is64 = g_is64;
    int dn = (int)edge_at(ei, (long long)EE + e, is64);
    int sn = (int)edge_at(ei, (long long)e, is64);
    int pos = atomicAdd(&g_cursor[dn], 1);
    g_col[pos] = sn;
}

// ---------------- aggregation (R5 pairwise HADD2; proven fastest) ----------------
__global__ __launch_bounds__(256) void k_agg16(const __half* __restrict__ h,
                                               __half* __restrict__ a) {
    int node = blockIdx.x * 8 + (threadIdx.x >> 5);
    if (node >= NN) return;
    int lane = threadIdx.x & 31;
    int g  = lane >> 3;
    int fl = lane & 7;
    int start = g_rowptr[node];
    int cnt   = g_cnt[node];
    const int* __restrict__ col = g_col + start;

    float acc[8];
#pragma unroll
    for (int q = 0; q < 8; q++) acc[q] = 0.f;

    for (int j = 2 * g; j < cnt; j += 8) {
        int c0 = col[j];
        uint4 v0 = *(const uint4*)(h + (size_t)c0 * DD + fl * 8);
        uint4 v1 = make_uint4(0u, 0u, 0u, 0u);
        if (j + 1 < cnt) {
            int c1 = col[j + 1];
            v1 = *(const uint4*)(h + (size_t)c1 * DD + fl * 8);
        }
        const __half2* a0 = (const __half2*)&v0;
        const __half2* a1 = (const __half2*)&v1;
#pragma unroll
        for (int q = 0; q < 4; q++) {
            float2 f = __half22float2(__hadd2(a0[q], a1[q]));
            acc[2 * q]     += f.x;
            acc[2 * q + 1] += f.y;
        }
    }
#pragma unroll
    for (int q = 0; q < 8; q++) {
        acc[q] += __shfl_xor_sync(0xffffffffu, acc[q], 8);
        acc[q] += __shfl_xor_sync(0xffffffffu, acc[q], 16);
    }
    if (g == 0) {
        float di = g_deginv[node];
        __half2 o[4];
#pragma unroll
        for (int q = 0; q < 4; q++)
            o[q] = __floats2half2_rn(acc[2 * q] * di, acc[2 * q + 1] * di);
        *(uint4*)(a + (size_t)node * DD + fl * 8) = *(uint4*)o;
    }
}

// ---------------- HMMA fused GEMM + optional fused layer-4 linear ----------------
#define XS 136
#define WS2 72
#define OFF_WS (128 * XS)                      // halves
#define OFF_WN (OFF_WS + 64 * WS2)
#define OFF_BIAS_B ((OFF_WN + 64 * WS2) * 2)   // bytes
#define OFF_W4_B (OFF_BIAS_B + 64 * 4)
#define SMEM_HM (OFF_W4_B + 128 * 4)

__global__ __launch_bounds__(256) void k_gemm_hmma(
    const __half* __restrict__ h16, const __half* __restrict__ a16,
    const float* __restrict__ Ws, const float* __restrict__ Wn,
    const float* __restrict__ bias, __half* __restrict__ out16,
    const float* __restrict__ ws4, const float* __restrict__ wn4,
    const float* __restrict__ b4, int do_lin4) {
    extern __shared__ char smem[];
    __half* sx = (__half*)smem;
    float* sbias = (float*)(smem + OFF_BIAS_B);
    float* sw4 = (float*)(smem + OFF_W4_B);       // [64] ws4, [64] wn4
    uint32_t sb = smem_u32(smem);

    int tid = threadIdx.x, wid = tid >> 5, lane = tid & 31;
    int base = blockIdx.x * 128;

    for (int idx = tid; idx < 4096; idx += 256) {
        int k = idx >> 6, n = idx & 63;
        sx[OFF_WS + k * WS2 + n] = __float2half_rn(Ws[idx]);
        sx[OFF_WN + k * WS2 + n] = __float2half_rn(Wn[idx]);
    }
    if (tid < 64) sbias[tid] = bias[tid];
    if (do_lin4 && tid < 64) { sw4[tid] = ws4[tid]; sw4[64 + tid] = wn4[tid]; }

    for (int idx = tid; idx < 128 * 16; idx += 256) {
        int r = idx >> 4, q = idx & 15;
        int node = base + r;
        uint4 v = make_uint4(0u, 0u, 0u, 0u);
        if (node < NN) {
            const __half* src = (q < 8) ? (h16 + (size_t)node * DD + q * 8)
                                        : (a16 + (size_t)node * DD + (q - 8) * 8);
            v = *(const uint4*)src;
        }
        *(uint4*)((char*)smem + (size_t)r * (XS * 2) + q * 16) = v;
    }
    __syncthreads();

    float acc[8][4];
#pragma unroll
    for (int nt = 0; nt < 8; nt++)
#pragma unroll
        for (int q = 0; q < 4; q++) acc[nt][q] = 0.f;

    int arow = wid * 16 + (lane & 15);
    int acolq = (lane >> 4) << 3;

#pragma unroll
    for (int ks = 0; ks < 8; ks++) {
        uint32_t a0, a1, a2, a3;
        ldsm_x4(a0, a1, a2, a3, sb + (arow * XS + ks * 16 + acolq) * 2);
        uint32_t wbase = (ks < 4) ? OFF_WS : OFF_WN;
        int kl = (ks & 3) * 16 + (lane & 15);
#pragma unroll
        for (int np = 0; np < 4; np++) {
            uint32_t b0, b1, b2, b3;
            ldsm_x4_t(b0, b1, b2, b3, sb + (wbase + kl * WS2 + np * 16 + acolq) * 2);
            mma16816(acc[np * 2],     a0, a1, a2, a3, b0, b1);
            mma16816(acc[np * 2 + 1], a0, a1, a2, a3, b2, b3);
        }
    }

    int r0 = base + wid * 16 + (lane >> 2);
    int r1 = r0 + 8;
    int cb = (lane & 3) * 2;
    float u0 = 0.f, t0 = 0.f, u1 = 0.f, t1 = 0.f;
#pragma unroll
    for (int nt = 0; nt < 8; nt++) {
        int c = nt * 8 + cb;
        float bb0 = sbias[c], bb1 = sbias[c + 1];
        float p0 = fmaxf(acc[nt][0] + bb0, 0.f);
        float p1 = fmaxf(acc[nt][1] + bb1, 0.f);
        float q0 = fmaxf(acc[nt][2] + bb0, 0.f);
        float q1 = fmaxf(acc[nt][3] + bb1, 0.f);
        if (out16) {
            if (r0 < NN)
                *(__half2*)(out16 + (size_t)r0 * DD + c) = __floats2half2_rn(p0, p1);
            if (r1 < NN)
                *(__half2*)(out16 + (size_t)r1 * DD + c) = __floats2half2_rn(q0, q1);
        }
        if (do_lin4) {
            u0 += p0 * sw4[c] + p1 * sw4[c + 1];
            t0 += p0 * sw4[64 + c] + p1 * sw4[64 + c + 1];
            u1 += q0 * sw4[c] + q1 * sw4[c + 1];
            t1 += q0 * sw4[64 + c] + q1 * sw4[64 + c + 1];
        }
    }
    if (do_lin4) {
        u0 += __shfl_xor_sync(0xffffffffu, u0, 1);
        u0 += __shfl_xor_sync(0xffffffffu, u0, 2);
        t0 += __shfl_xor_sync(0xffffffffu, t0, 1);
        t0 += __shfl_xor_sync(0xffffffffu, t0, 2);
        u1 += __shfl_xor_sync(0xffffffffu, u1, 1);
        u1 += __shfl_xor_sync(0xffffffffu, u1, 2);
        t1 += __shfl_xor_sync(0xffffffffu, t1, 1);
        t1 += __shfl_xor_sync(0xffffffffu, t1, 2);
        if ((lane & 3) == 0) {
            float bb = b4[0];
            if (r0 < NN) { g_u4[r0] = u0 + bb; g_t4[r0] = t0; }
            if (r1 < NN) { g_u4[r1] = u1 + bb; g_t4[r1] = t1; }
        }
    }
}

// ---------------- layer 4 output: sigmoid(u4 + deginv * sum t4[nbrs]) ----------------
__global__ void k_out4(float* __restrict__ out) {
    int node = blockIdx.x * 8 + (threadIdx.x >> 5);
    if (node >= NN) return;
    int lane = threadIdx.x & 31;
    int start = g_rowptr[node];
    int cnt   = g_cnt[node];
    float acc = 0.f;
    for (int j = lane; j < cnt; j += 32) acc += g_t4[g_col[start + j]];
#pragma unroll
    for (int o = 16; o; o >>= 1) acc += __shfl_down_sync(0xffffffffu, acc, o);
    if (lane == 0) {
        float z = g_u4[node] + g_deginv[node] * acc;
        out[node] = 1.0f / (1.0f + expf(-z));
    }
}

// ---------------- launch ----------------
extern "C" void kernel_launch(void* const* d_in, const int* in_sizes, int n_in,
                              void* d_out, int out_size) {
    const float* x   = (const float*)d_in[0];
    const void*  ei  = d_in[1];
    const float* Ws1 = (const float*)d_in[2];
    const float* Wn1 = (const float*)d_in[3];
    const float* b1  = (const float*)d_in[4];
    const float* Ws2 = (const float*)d_in[5];
    const float* Wn2 = (const float*)d_in[6];
    const float* b2  = (const float*)d_in[7];
    const float* Ws3 = (const float*)d_in[8];
    const float* Wn3 = (const float*)d_in[9];
    const float* b3  = (const float*)d_in[10];
    const float* Ws4 = (const float*)d_in[11];
    const float* Wn4 = (const float*)d_in[12];
    const float* b4  = (const float*)d_in[13];
    float* out = (float*)d_out;

    static __half *pHa = nullptr, *pHb = nullptr, *pAg = nullptr;
    if (!pHa) {
        void* p;
        cudaGetSymbolAddress(&p, g_h16a);   pHa = (__half*)p;
        cudaGetSymbolAddress(&p, g_h16b);   pHb = (__half*)p;
        cudaGetSymbolAddress(&p, g_agg16);  pAg = (__half*)p;
        cudaFuncSetAttribute(k_gemm_hmma, cudaFuncAttributeMaxDynamicSharedMemorySize,
                             SMEM_HM);
    }

    const int nbScan = (NN + 1023) / 1024;
    const int gridE  = EE / 256;
    const int gridN8 = (NN + 7) / 8;
    const int gridG  = (NN + 127) / 128;
    const int gridC  = (NN * DD / 4 + 255) / 256;

    // pre (conv + zero cnt + detect) + CSR build
    k_pre<<<gridC, 256>>>(x, pHa, ei);
    k_hist<<<gridE, 256>>>(ei);
    k_scan_partial<<<nbScan, 1024>>>();
    k_scan_blk<<<1, 128>>>(nbScan);
    k_scan_add<<<nbScan, 1024>>>();
    k_fill<<<gridE, 256>>>(ei);

    // layer 1
    k_agg16<<<gridN8, 256>>>(pHa, pAg);
    k_gemm_hmma<<<gridG, 256, SMEM_HM>>>(pHa, pAg, Ws1, Wn1, b1, pHb,
                                         Ws4, Wn4, b4, 0);
    // layer 2
    k_agg16<<<gridN8, 256>>>(pHb, pAg);
    k_gemm_hmma<<<gridG, 256, SMEM_HM>>>(pHb, pAg, Ws2, Wn2, b2, pHa,
                                         Ws4, Wn4, b4, 0);
    // layer 3 (+ fused layer-4 linear; no layer-3 output store needed)
    k_agg16<<<gridN8, 256>>>(pHa, pAg);
    k_gemm_hmma<<<gridG, 256, SMEM_HM>>>(pHa, pAg, Ws3, Wn3, b3, ((__half*)0),
                                         Ws4, Wn4, b4, 1);
    // layer 4 aggregation + sigmoid
    k_out4<<<gridN8, 256>>>(out);
}

// round 9
// speedup vs baseline: 1.2673x; 1.1140x over previous
#include <cuda_runtime.h>
#include <cuda_fp16.h>
#include <cstdint>

#define NN 100000
#define EE 1600000
#define DD 64

// ---------------- scratch (device globals; no runtime allocation) ----------------
__device__ __align__(256) __half g_h16a [NN * DD];
__device__ __align__(256) __half g_h16b [NN * DD];
__device__ __align__(256) __half g_agg16[NN * DD];
__device__ __align__(256) __half g_w16[6 * 4096];   // Ws1,Wn1,Ws2,Wn2,Ws3,Wn3 fp16
__device__ int   g_cnt2[NN];     // atomic histogram (self-cleaning; starts zero)
__device__ int   g_cnt[NN];      // plain per-node degree
__device__ int   g_rowptr[NN];
__device__ int   g_cursor[NN];
__device__ int   g_col[EE];
__device__ float g_deginv[NN];
__device__ int   g_blksum[128];
__device__ float g_t4[NN];
__device__ float g_u4[NN];

// ---------------- helpers ----------------
__device__ __forceinline__ uint32_t smem_u32(const void* p) {
    uint32_t a;
    asm("{ .reg .u64 t; cvta.to.shared.u64 t, %1; cvt.u32.u64 %0, t; }" : "=r"(a) : "l"(p));
    return a;
}
__device__ __forceinline__ long long edge_at(const void* ei, long long idx, int is64) {
    if (is64) return ((const long long*)ei)[idx];
    return (long long)((const int*)ei)[idx];
}
// per-warp dtype detection: high words of first 32 int64 pairs all zero => int64
__device__ __forceinline__ int detect64(const void* ei) {
    const unsigned* w = (const unsigned*)ei;
    unsigned lane = threadIdx.x & 31;
    bool z = (w[2 * lane + 1] == 0u);
    return __all_sync(0xffffffffu, z) ? 1 : 0;
}
__device__ __forceinline__ void ldsm_x4(uint32_t& r0, uint32_t& r1, uint32_t& r2,
                                        uint32_t& r3, uint32_t addr) {
    asm volatile("ldmatrix.sync.aligned.m8n8.x4.shared.b16 {%0,%1,%2,%3}, [%4];"
                 : "=r"(r0), "=r"(r1), "=r"(r2), "=r"(r3) : "r"(addr));
}
__device__ __forceinline__ void ldsm_x4_t(uint32_t& r0, uint32_t& r1, uint32_t& r2,
                                          uint32_t& r3, uint32_t addr) {
    asm volatile("ldmatrix.sync.aligned.m8n8.x4.trans.shared.b16 {%0,%1,%2,%3}, [%4];"
                 : "=r"(r0), "=r"(r1), "=r"(r2), "=r"(r3) : "r"(addr));
}
__device__ __forceinline__ void mma16816(float* d, uint32_t a0, uint32_t a1, uint32_t a2,
                                         uint32_t a3, uint32_t b0, uint32_t b1) {
    asm volatile(
        "mma.sync.aligned.m16n8k16.row.col.f32.f16.f16.f32 "
        "{%0,%1,%2,%3}, {%4,%5,%6,%7}, {%8,%9}, {%0,%1,%2,%3};"
        : "+f"(d[0]), "+f"(d[1]), "+f"(d[2]), "+f"(d[3])
        : "r"(a0), "r"(a1), "r"(a2), "r"(a3), "r"(b0), "r"(b1));
}
__device__ __forceinline__ int warp_iscan(int v, int lane) {
#pragma unroll
    for (int off = 1; off < 32; off <<= 1) {
        int t = __shfl_up_sync(0xffffffffu, v, off);
        if (lane >= off) v += t;
    }
    return v;
}

// ---------------- weight pre-conversion fp32 -> fp16 (24 blocks x 256) ----------------
__global__ void k_wconv(const float* __restrict__ Ws1, const float* __restrict__ Wn1,
                        const float* __restrict__ Ws2, const float* __restrict__ Wn2,
                        const float* __restrict__ Ws3, const float* __restrict__ Wn3) {
    const float* srcs[6] = {Ws1, Wn1, Ws2, Wn2, Ws3, Wn3};
    int m = blockIdx.x >> 2;          // matrix 0..5
    int seg = blockIdx.x & 3;         // quarter 0..3
    const float* s = srcs[m];
    int base = seg * 1024;
    for (int i = threadIdx.x; i < 1024; i += 256)
        g_w16[m * 4096 + base + i] = __float2half_rn(s[base + i]);
}

// ---------------- hist + conv + detect (6250 blocks x 256 = 1.6M threads) ------------
__global__ void k_hist(const void* __restrict__ ei, const float* __restrict__ x,
                       __half* __restrict__ o) {
    int is64 = detect64(ei);
    int e = blockIdx.x * 256 + threadIdx.x;
    int d = (int)edge_at(ei, (long long)EE + e, is64);
    atomicAdd(&g_cnt2[d], 1);
    // NN*DD/4 == EE: every thread converts exactly one float4 of x
    float4 v = ((const float4*)x)[e];
    ((__half2*)o)[2 * e]     = __floats2half2_rn(v.x, v.y);
    ((__half2*)o)[2 * e + 1] = __floats2half2_rn(v.z, v.w);
}

// ---------------- scan (1024-thr shuffle scan; reads+clears g_cnt2) ----------------
__global__ void k_scan_partial() {
    __shared__ int wsum[32];
    int i = blockIdx.x * 1024 + threadIdx.x;
    int lane = threadIdx.x & 31, w = threadIdx.x >> 5;
    int v = 0;
    if (i < NN) {
        v = g_cnt2[i];
        g_cnt2[i] = 0;        // self-clean for next replay
        g_cnt[i] = v;         // plain copy for agg/deginv
    }
    int s = warp_iscan(v, lane);
    if (lane == 31) wsum[w] = s;
    __syncthreads();
    if (w == 0) wsum[lane] = warp_iscan(wsum[lane], lane);
    __syncthreads();
    int incl = s + ((w > 0) ? wsum[w - 1] : 0);
    if (i < NN) g_rowptr[i] = incl - v;
    if (threadIdx.x == 1023) g_blksum[blockIdx.x] = incl;
}

// scan_add with in-kernel block-prefix (replaces k_scan_blk)
__global__ void k_scan_add(int nb) {
    __shared__ int sblk[128];
    __shared__ int swsum[4];
    int t = threadIdx.x;
    if (t < 128) {
        int lane = t & 31, w = t >> 5;
        int v = (t < nb) ? g_blksum[t] : 0;
        int s = warp_iscan(v, lane);
        sblk[t] = s - v;
        if (lane == 31) swsum[w] = s;
    }
    __syncthreads();
    if (t == 0) {
        int run = 0;
        for (int q = 0; q < 4; q++) { int x = swsum[q]; swsum[q] = run; run += x; }
    }
    __syncthreads();
    int boff = sblk[blockIdx.x] + swsum[blockIdx.x >> 5];
    int i = blockIdx.x * 1024 + t;
    if (i < NN) {
        int r = g_rowptr[i] + boff;
        g_rowptr[i] = r;
        g_cursor[i] = r;
        int c = g_cnt[i];
        g_deginv[i] = 1.0f / (float)(c > 0 ? c : 1);
    }
}

__global__ void k_fill(const void* __restrict__ ei) {
    int is64 = detect64(ei);
    int e = blockIdx.x * 256 + threadIdx.x;
    int dn = (int)edge_at(ei, (long long)EE + e, is64);
    int sn = (int)edge_at(ei, (long long)e, is64);
    int pos = atomicAdd(&g_cursor[dn], 1);
    g_col[pos] = sn;
}

// ---------------- aggregation (pairwise HADD2; proven fastest) ----------------
__global__ __launch_bounds__(256) void k_agg16(const __half* __restrict__ h,
                                               __half* __restrict__ a) {
    int node = blockIdx.x * 8 + (threadIdx.x >> 5);
    if (node >= NN) return;
    int lane = threadIdx.x & 31;
    int g  = lane >> 3;
    int fl = lane & 7;
    int start = g_rowptr[node];
    int cnt   = g_cnt[node];
    const int* __restrict__ col = g_col + start;

    float acc[8];
#pragma unroll
    for (int q = 0; q < 8; q++) acc[q] = 0.f;

    for (int j = 2 * g; j < cnt; j += 8) {
        int c0 = col[j];
        uint4 v0 = *(const uint4*)(h + (size_t)c0 * DD + fl * 8);
        uint4 v1 = make_uint4(0u, 0u, 0u, 0u);
        if (j + 1 < cnt) {
            int c1 = col[j + 1];
            v1 = *(const uint4*)(h + (size_t)c1 * DD + fl * 8);
        }
        const __half2* a0 = (const __half2*)&v0;
        const __half2* a1 = (const __half2*)&v1;
#pragma unroll
        for (int q = 0; q < 4; q++) {
            float2 f = __half22float2(__hadd2(a0[q], a1[q]));
            acc[2 * q]     += f.x;
            acc[2 * q + 1] += f.y;
        }
    }
#pragma unroll
    for (int q = 0; q < 8; q++) {
        acc[q] += __shfl_xor_sync(0xffffffffu, acc[q], 8);
        acc[q] += __shfl_xor_sync(0xffffffffu, acc[q], 16);
    }
    if (g == 0) {
        float di = g_deginv[node];
        __half2 o[4];
#pragma unroll
        for (int q = 0; q < 4; q++)
            o[q] = __floats2half2_rn(acc[2 * q] * di, acc[2 * q + 1] * di);
        *(uint4*)(a + (size_t)node * DD + fl * 8) = *(uint4*)o;
    }
}

// ---------------- HMMA fused GEMM + optional fused layer-4 linear ----------------
#define XS 136
#define WS2 72
#define OFF_WS (128 * XS)                      // halves
#define OFF_WN (OFF_WS + 64 * WS2)
#define OFF_BIAS_B ((OFF_WN + 64 * WS2) * 2)   // bytes
#define OFF_W4_B (OFF_BIAS_B + 64 * 4)
#define SMEM_HM (OFF_W4_B + 128 * 4)

__global__ __launch_bounds__(256) void k_gemm_hmma(
    const __half* __restrict__ h16, const __half* __restrict__ a16,
    int lidx, const float* __restrict__ bias, __half* __restrict__ out16,
    const float* __restrict__ ws4, const float* __restrict__ wn4,
    const float* __restrict__ b4, int do_lin4) {
    extern __shared__ char smem[];
    __half* sx = (__half*)smem;
    float* sbias = (float*)(smem + OFF_BIAS_B);
    float* sw4 = (float*)(smem + OFF_W4_B);
    uint32_t sb = smem_u32(smem);

    int tid = threadIdx.x, wid = tid >> 5, lane = tid & 31;
    int base = blockIdx.x * 128;

    // stage fp16 weights (vectorized uint4 copies)
    const __half* w16 = g_w16 + lidx * 8192;   // Ws then Wn
    for (int idx = tid; idx < 1024; idx += 256) {
        int m = idx >> 9;            // 0 = Ws, 1 = Wn
        int r = idx & 511;           // uint4 index within matrix
        int k = r >> 3, ch = r & 7;
        uint4 v = ((const uint4*)(w16 + m * 4096))[r];
        *(uint4*)&sx[(m ? OFF_WN : OFF_WS) + k * WS2 + ch * 8] = v;
    }
    if (tid < 64) sbias[tid] = bias[tid];
    if (do_lin4 && tid < 64) { sw4[tid] = ws4[tid]; sw4[64 + tid] = wn4[tid]; }

    for (int idx = tid; idx < 128 * 16; idx += 256) {
        int r = idx >> 4, q = idx & 15;
        int node = base + r;
        uint4 v = make_uint4(0u, 0u, 0u, 0u);
        if (node < NN) {
            const __half* src = (q < 8) ? (h16 + (size_t)node * DD + q * 8)
                                        : (a16 + (size_t)node * DD + (q - 8) * 8);
            v = *(const uint4*)src;
        }
        *(uint4*)((char*)smem + (size_t)r * (XS * 2) + q * 16) = v;
    }
    __syncthreads();

    float acc[8][4];
#pragma unroll
    for (int nt = 0; nt < 8; nt++)
#pragma unroll
        for (int q = 0; q < 4; q++) acc[nt][q] = 0.f;

    int arow = wid * 16 + (lane & 15);
    int acolq = (lane >> 4) << 3;

#pragma unroll
    for (int ks = 0; ks < 8; ks++) {
        uint32_t a0, a1, a2, a3;
        ldsm_x4(a0, a1, a2, a3, sb + (arow * XS + ks * 16 + acolq) * 2);
        uint32_t wbase = (ks < 4) ? OFF_WS : OFF_WN;
        int kl = (ks & 3) * 16 + (lane & 15);
#pragma unroll
        for (int np = 0; np < 4; np++) {
            uint32_t b0, b1, b2, b3;
            ldsm_x4_t(b0, b1, b2, b3, sb + (wbase + kl * WS2 + np * 16 + acolq) * 2);
            mma16816(acc[np * 2],     a0, a1, a2, a3, b0, b1);
            mma16816(acc[np * 2 + 1], a0, a1, a2, a3, b2, b3);
        }
    }

    int r0 = base + wid * 16 + (lane >> 2);
    int r1 = r0 + 8;
    int cb = (lane & 3) * 2;
    float u0 = 0.f, t0 = 0.f, u1 = 0.f, t1 = 0.f;
#pragma unroll
    for (int nt = 0; nt < 8; nt++) {
        int c = nt * 8 + cb;
        float bb0 = sbias[c], bb1 = sbias[c + 1];
        float p0 = fmaxf(acc[nt][0] + bb0, 0.f);
        float p1 = fmaxf(acc[nt][1] + bb1, 0.f);
        float q0 = fmaxf(acc[nt][2] + bb0, 0.f);
        float q1 = fmaxf(acc[nt][3] + bb1, 0.f);
        if (out16) {
            if (r0 < NN)
                *(__half2*)(out16 + (size_t)r0 * DD + c) = __floats2half2_rn(p0, p1);
            if (r1 < NN)
                *(__half2*)(out16 + (size_t)r1 * DD + c) = __floats2half2_rn(q0, q1);
        }
        if (do_lin4) {
            u0 += p0 * sw4[c] + p1 * sw4[c + 1];
            t0 += p0 * sw4[64 + c] + p1 * sw4[64 + c + 1];
            u1 += q0 * sw4[c] + q1 * sw4[c + 1];
            t1 += q0 * sw4[64 + c] + q1 * sw4[64 + c + 1];
        }
    }
    if (do_lin4) {
        u0 += __shfl_xor_sync(0xffffffffu, u0, 1);
        u0 += __shfl_xor_sync(0xffffffffu, u0, 2);
        t0 += __shfl_xor_sync(0xffffffffu, t0, 1);
        t0 += __shfl_xor_sync(0xffffffffu, t0, 2);
        u1 += __shfl_xor_sync(0xffffffffu, u1, 1);
        u1 += __shfl_xor_sync(0xffffffffu, u1, 2);
        t1 += __shfl_xor_sync(0xffffffffu, t1, 1);
        t1 += __shfl_xor_sync(0xffffffffu, t1, 2);
        if ((lane & 3) == 0) {
            float bb = b4[0];
            if (r0 < NN) { g_u4[r0] = u0 + bb; g_t4[r0] = t0; }
            if (r1 < NN) { g_u4[r1] = u1 + bb; g_t4[r1] = t1; }
        }
    }
}

// ---------------- layer 4 output: sigmoid(u4 + deginv * sum t4[nbrs]) ----------------
__global__ void k_out4(float* __restrict__ out) {
    int node = blockIdx.x * 8 + (threadIdx.x >> 5);
    if (node >= NN) return;
    int lane = threadIdx.x & 31;
    int start = g_rowptr[node];
    int cnt   = g_cnt[node];
    float acc = 0.f;
    for (int j = lane; j < cnt; j += 32) acc += g_t4[g_col[start + j]];
#pragma unroll
    for (int o = 16; o; o >>= 1) acc += __shfl_down_sync(0xffffffffu, acc, o);
    if (lane == 0) {
        float z = g_u4[node] + g_deginv[node] * acc;
        out[node] = 1.0f / (1.0f + expf(-z));
    }
}

// ---------------- launch ----------------
extern "C" void kernel_launch(void* const* d_in, const int* in_sizes, int n_in,
                              void* d_out, int out_size) {
    const float* x   = (const float*)d_in[0];
    const void*  ei  = d_in[1];
    const float* Ws1 = (const float*)d_in[2];
    const float* Wn1 = (const float*)d_in[3];
    const float* b1  = (const float*)d_in[4];
    const float* Ws2 = (const float*)d_in[5];
    const float* Wn2 = (const float*)d_in[6];
    const float* b2  = (const float*)d_in[7];
    const float* Ws3 = (const float*)d_in[8];
    const float* Wn3 = (const float*)d_in[9];
    const float* b3  = (const float*)d_in[10];
    const float* Ws4 = (const float*)d_in[11];
    const float* Wn4 = (const float*)d_in[12];
    const float* b4  = (const float*)d_in[13];
    float* out = (float*)d_out;

    static __half *pHa = nullptr, *pHb = nullptr, *pAg = nullptr;
    if (!pHa) {
        void* p;
        cudaGetSymbolAddress(&p, g_h16a);   pHa = (__half*)p;
        cudaGetSymbolAddress(&p, g_h16b);   pHb = (__half*)p;
        cudaGetSymbolAddress(&p, g_agg16);  pAg = (__half*)p;
        cudaFuncSetAttribute(k_gemm_hmma, cudaFuncAttributeMaxDynamicSharedMemorySize,
                             SMEM_HM);
    }

    const int nbScan = (NN + 1023) / 1024;
    const int gridE  = EE / 256;
    const int gridN8 = (NN + 7) / 8;
    const int gridG  = (NN + 127) / 128;

    // weight conversion + CSR build (hist also converts x, detects dtype per block)
    k_wconv<<<24, 256>>>(Ws1, Wn1, Ws2, Wn2, Ws3, Wn3);
    k_hist<<<gridE, 256>>>(ei, x, pHa);
    k_scan_partial<<<nbScan, 1024>>>();
    k_scan_add<<<nbScan, 1024>>>(nbScan);
    k_fill<<<gridE, 256>>>(ei);

    // layer 1
    k_agg16<<<gridN8, 256>>>(pHa, pAg);
    k_gemm_hmma<<<gridG, 256, SMEM_HM>>>(pHa, pAg, 0, b1, pHb, Ws4, Wn4, b4, 0);
    // layer 2
    k_agg16<<<gridN8, 256>>>(pHb, pAg);
    k_gemm_hmma<<<gridG, 256, SMEM_HM>>>(pHb, pAg, 1, b2, pHa, Ws4, Wn4, b4, 0);
    // layer 3 (+ fused layer-4 linear; no layer-3 output store)
    k_agg16<<<gridN8, 256>>>(pHa, pAg);
    k_gemm_hmma<<<gridG, 256, SMEM_HM>>>(pHa, pAg, 2, b3, ((__half*)0), Ws4, Wn4, b4, 1);
    // layer 4 aggregation + sigmoid
    k_out4<<<gridN8, 256>>>(out);
}

// round 10
// speedup vs baseline: 1.3081x; 1.0323x over previous
#include <cuda_runtime.h>
#include <cuda_fp16.h>
#include <cstdint>

#define NN 100000
#define EE 1600000
#define DD 64
#define GRID_E 6250

// ---------------- scratch (device globals; no runtime allocation) ----------------
__device__ __align__(256) __half g_h16a [NN * DD];
__device__ __align__(256) __half g_h16b [NN * DD];
__device__ __align__(256) __half g_agg16[NN * DD];
__device__ __align__(256) __half g_w16[6 * 4096];   // Ws1,Wn1,Ws2,Wn2,Ws3,Wn3 fp16
__device__ int   g_cnt2[NN];     // atomic histogram (self-cleaning; starts zero)
__device__ int   g_cnt[NN];      // plain per-node degree
__device__ int   g_rowptr[NN];
__device__ int   g_cursor[NN];
__device__ int   g_col[EE];
__device__ float g_deginv[NN];
__device__ float g_t4[NN];
__device__ float g_u4[NN];
__device__ int   g_alloc;        // segment allocator (self-cleaning)
__device__ int   g_done;         // block done-counter (self-cleaning)

// ---------------- helpers ----------------
__device__ __forceinline__ uint32_t smem_u32(const void* p) {
    uint32_t a;
    asm("{ .reg .u64 t; cvta.to.shared.u64 t, %1; cvt.u32.u64 %0, t; }" : "=r"(a) : "l"(p));
    return a;
}
__device__ __forceinline__ long long edge_at(const void* ei, long long idx, int is64) {
    if (is64) return ((const long long*)ei)[idx];
    return (long long)((const int*)ei)[idx];
}
// per-warp dtype detection: high words of first 32 int64 pairs all zero => int64
__device__ __forceinline__ int detect64(const void* ei) {
    const unsigned* w = (const unsigned*)ei;
    unsigned lane = threadIdx.x & 31;
    bool z = (w[2 * lane + 1] == 0u);
    return __all_sync(0xffffffffu, z) ? 1 : 0;
}
__device__ __forceinline__ void ldsm_x4(uint32_t& r0, uint32_t& r1, uint32_t& r2,
                                        uint32_t& r3, uint32_t addr) {
    asm volatile("ldmatrix.sync.aligned.m8n8.x4.shared.b16 {%0,%1,%2,%3}, [%4];"
                 : "=r"(r0), "=r"(r1), "=r"(r2), "=r"(r3) : "r"(addr));
}
__device__ __forceinline__ void ldsm_x4_t(uint32_t& r0, uint32_t& r1, uint32_t& r2,
                                          uint32_t& r3, uint32_t addr) {
    asm volatile("ldmatrix.sync.aligned.m8n8.x4.trans.shared.b16 {%0,%1,%2,%3}, [%4];"
                 : "=r"(r0), "=r"(r1), "=r"(r2), "=r"(r3) : "r"(addr));
}
__device__ __forceinline__ void mma16816(float* d, uint32_t a0, uint32_t a1, uint32_t a2,
                                         uint32_t a3, uint32_t b0, uint32_t b1) {
    asm volatile(
        "mma.sync.aligned.m16n8k16.row.col.f32.f16.f16.f32 "
        "{%0,%1,%2,%3}, {%4,%5,%6,%7}, {%8,%9}, {%0,%1,%2,%3};"
        : "+f"(d[0]), "+f"(d[1]), "+f"(d[2]), "+f"(d[3])
        : "r"(a0), "r"(a1), "r"(a2), "r"(a3), "r"(b0), "r"(b1));
}
__device__ __forceinline__ int warp_iscan(int v, int lane) {
#pragma unroll
    for (int off = 1; off < 32; off <<= 1) {
        int t = __shfl_up_sync(0xffffffffu, v, off);
        if (lane >= off) v += t;
    }
    return v;
}

// ---------------- hist + x conv + weight conv (6250 edge blocks + 24 weight blocks) --
__global__ void k_hist(const void* __restrict__ ei, const float* __restrict__ x,
                       __half* __restrict__ o,
                       const float* __restrict__ Ws1, const float* __restrict__ Wn1,
                       const float* __restrict__ Ws2, const float* __restrict__ Wn2,
                       const float* __restrict__ Ws3, const float* __restrict__ Wn3) {
    if (blockIdx.x >= GRID_E) {
        // weight conversion fp32 -> fp16
        int mb = blockIdx.x - GRID_E;       // 0..23
        int m = mb >> 2, seg = mb & 3;
        const float* srcs[6] = {Ws1, Wn1, Ws2, Wn2, Ws3, Wn3};
        const float* s = srcs[m];
        int base = seg * 1024;
        for (int i = threadIdx.x; i < 1024; i += 256)
            g_w16[m * 4096 + base + i] = __float2half_rn(s[base + i]);
        return;
    }
    int is64 = detect64(ei);
    int e = blockIdx.x * 256 + threadIdx.x;
    int d = (int)edge_at(ei, (long long)EE + e, is64);
    atomicAdd(&g_cnt2[d], 1);
    // NN*DD/4 == EE: every edge thread converts exactly one float4 of x
    float4 v = ((const float4*)x)[e];
    ((__half2*)o)[2 * e]     = __floats2half2_rn(v.x, v.y);
    ((__half2*)o)[2 * e + 1] = __floats2half2_rn(v.z, v.w);
}

// ---------------- segment allocation (replaces the prefix scan entirely) ----------
// CSR only needs DISJOINT segments, not ordered ones: one atomicAdd per warp.
__global__ void k_alloc() {
    int i = blockIdx.x * 256 + threadIdx.x;
    int lane = threadIdx.x & 31;
    int v = 0;
    if (i < NN) {
        v = g_cnt2[i];
        g_cnt2[i] = 0;                      // self-clean for next replay
        g_cnt[i] = v;
        g_deginv[i] = 1.0f / (float)(v > 0 ? v : 1);
    }
    int s = warp_iscan(v, lane);            // inclusive within warp
    int wtot = __shfl_sync(0xffffffffu, s, 31);
    int base = 0;
    if (lane == 31) base = atomicAdd(&g_alloc, wtot);
    base = __shfl_sync(0xffffffffu, base, 31);
    if (i < NN) {
        int start = base + s - v;
        g_rowptr[i] = start;
        g_cursor[i] = start;
    }
    __syncthreads();
    if (threadIdx.x == 0) {
        int d = atomicAdd(&g_done, 1);
        if (d == (int)gridDim.x - 1) { g_alloc = 0; g_done = 0; }  // self-clean
    }
}

__global__ void k_fill(const void* __restrict__ ei) {
    int is64 = detect64(ei);
    int e = blockIdx.x * 256 + threadIdx.x;
    int dn = (int)edge_at(ei, (long long)EE + e, is64);
    int sn = (int)edge_at(ei, (long long)e, is64);
    int pos = atomicAdd(&g_cursor[dn], 1);
    g_col[pos] = sn;
}

// ---------------- aggregation (pairwise HADD2; proven fastest) ----------------
__global__ __launch_bounds__(256) void k_agg16(const __half* __restrict__ h,
                                               __half* __restrict__ a) {
    int node = blockIdx.x * 8 + (threadIdx.x >> 5);
    if (node >= NN) return;
    int lane = threadIdx.x & 31;
    int g  = lane >> 3;
    int fl = lane & 7;
    int start = g_rowptr[node];
    int cnt   = g_cnt[node];
    const int* __restrict__ col = g_col + start;

    float acc[8];
#pragma unroll
    for (int q = 0; q < 8; q++) acc[q] = 0.f;

    for (int j = 2 * g; j < cnt; j += 8) {
        int c0 = col[j];
        uint4 v0 = *(const uint4*)(h + (size_t)c0 * DD + fl * 8);
        uint4 v1 = make_uint4(0u, 0u, 0u, 0u);
        if (j + 1 < cnt) {
            int c1 = col[j + 1];
            v1 = *(const uint4*)(h + (size_t)c1 * DD + fl * 8);
        }
        const __half2* a0 = (const __half2*)&v0;
        const __half2* a1 = (const __half2*)&v1;
#pragma unroll
        for (int q = 0; q < 4; q++) {
            float2 f = __half22float2(__hadd2(a0[q], a1[q]));
            acc[2 * q]     += f.x;
            acc[2 * q + 1] += f.y;
        }
    }
#pragma unroll
    for (int q = 0; q < 8; q++) {
        acc[q] += __shfl_xor_sync(0xffffffffu, acc[q], 8);
        acc[q] += __shfl_xor_sync(0xffffffffu, acc[q], 16);
    }
    if (g == 0) {
        float di = g_deginv[node];
        __half2 o[4];
#pragma unroll
        for (int q = 0; q < 4; q++)
            o[q] = __floats2half2_rn(acc[2 * q] * di, acc[2 * q + 1] * di);
        *(uint4*)(a + (size_t)node * DD + fl * 8) = *(uint4*)o;
    }
}

// ---------------- HMMA fused GEMM + optional fused layer-4 linear ----------------
#define XS 136
#define WS2 72
#define OFF_WS (128 * XS)                      // halves
#define OFF_WN (OFF_WS + 64 * WS2)
#define OFF_BIAS_B ((OFF_WN + 64 * WS2) * 2)   // bytes
#define OFF_W4_B (OFF_BIAS_B + 64 * 4)
#define SMEM_HM (OFF_W4_B + 128 * 4)

__global__ __launch_bounds__(256) void k_gemm_hmma(
    const __half* __restrict__ h16, const __half* __restrict__ a16,
    int lidx, const float* __restrict__ bias, __half* __restrict__ out16,
    const float* __restrict__ ws4, const float* __restrict__ wn4,
    const float* __restrict__ b4, int do_lin4) {
    extern __shared__ char smem[];
    __half* sx = (__half*)smem;
    float* sbias = (float*)(smem + OFF_BIAS_B);
    float* sw4 = (float*)(smem + OFF_W4_B);
    uint32_t sb = smem_u32(smem);

    int tid = threadIdx.x, wid = tid >> 5, lane = tid & 31;
    int base = blockIdx.x * 128;

    // stage fp16 weights (vectorized uint4 copies)
    const __half* w16 = g_w16 + lidx * 8192;   // Ws then Wn
    for (int idx = tid; idx < 1024; idx += 256) {
        int m = idx >> 9;            // 0 = Ws, 1 = Wn
        int r = idx & 511;           // uint4 index within matrix
        int k = r >> 3, ch = r & 7;
        uint4 v = ((const uint4*)(w16 + m * 4096))[r];
        *(uint4*)&sx[(m ? OFF_WN : OFF_WS) + k * WS2 + ch * 8] = v;
    }
    if (tid < 64) sbias[tid] = bias[tid];
    if (do_lin4 && tid < 64) { sw4[tid] = ws4[tid]; sw4[64 + tid] = wn4[tid]; }

    for (int idx = tid; idx < 128 * 16; idx += 256) {
        int r = idx >> 4, q = idx & 15;
        int node = base + r;
        uint4 v = make_uint4(0u, 0u, 0u, 0u);
        if (node < NN) {
            const __half* src = (q < 8) ? (h16 + (size_t)node * DD + q * 8)
                                        : (a16 + (size_t)node * DD + (q - 8) * 8);
            v = *(const uint4*)src;
        }
        *(uint4*)((char*)smem + (size_t)r * (XS * 2) + q * 16) = v;
    }
    __syncthreads();

    float acc[8][4];
#pragma unroll
    for (int nt = 0; nt < 8; nt++)
#pragma unroll
        for (int q = 0; q < 4; q++) acc[nt][q] = 0.f;

    int arow = wid * 16 + (lane & 15);
    int acolq = (lane >> 4) << 3;

#pragma unroll
    for (int ks = 0; ks < 8; ks++) {
        uint32_t a0, a1, a2, a3;
        ldsm_x4(a0, a1, a2, a3, sb + (arow * XS + ks * 16 + acolq) * 2);
        uint32_t wbase = (ks < 4) ? OFF_WS : OFF_WN;
        int kl = (ks & 3) * 16 + (lane & 15);
#pragma unroll
        for (int np = 0; np < 4; np++) {
            uint32_t b0, b1, b2, b3;
            ldsm_x4_t(b0, b1, b2, b3, sb + (wbase + kl * WS2 + np * 16 + acolq) * 2);
            mma16816(acc[np * 2],     a0, a1, a2, a3, b0, b1);
            mma16816(acc[np * 2 + 1], a0, a1, a2, a3, b2, b3);
        }
    }

    int r0 = base + wid * 16 + (lane >> 2);
    int r1 = r0 + 8;
    int cb = (lane & 3) * 2;
    float u0 = 0.f, t0 = 0.f, u1 = 0.f, t1 = 0.f;
#pragma unroll
    for (int nt = 0; nt < 8; nt++) {
        int c = nt * 8 + cb;
        float bb0 = sbias[c], bb1 = sbias[c + 1];
        float p0 = fmaxf(acc[nt][0] + bb0, 0.f);
        float p1 = fmaxf(acc[nt][1] + bb1, 0.f);
        float q0 = fmaxf(acc[nt][2] + bb0, 0.f);
        float q1 = fmaxf(acc[nt][3] + bb1, 0.f);
        if (out16) {
            if (r0 < NN)
                *(__half2*)(out16 + (size_t)r0 * DD + c) = __floats2half2_rn(p0, p1);
            if (r1 < NN)
                *(__half2*)(out16 + (size_t)r1 * DD + c) = __floats2half2_rn(q0, q1);
        }
        if (do_lin4) {
            u0 += p0 * sw4[c] + p1 * sw4[c + 1];
            t0 += p0 * sw4[64 + c] + p1 * sw4[64 + c + 1];
            u1 += q0 * sw4[c] + q1 * sw4[c + 1];
            t1 += q0 * sw4[64 + c] + q1 * sw4[64 + c + 1];
        }
    }
    if (do_lin4) {
        u0 += __shfl_xor_sync(0xffffffffu, u0, 1);
        u0 += __shfl_xor_sync(0xffffffffu, u0, 2);
        t0 += __shfl_xor_sync(0xffffffffu, t0, 1);
        t0 += __shfl_xor_sync(0xffffffffu, t0, 2);
        u1 += __shfl_xor_sync(0xffffffffu, u1, 1);
        u1 += __shfl_xor_sync(0xffffffffu, u1, 2);
        t1 += __shfl_xor_sync(0xffffffffu, t1, 1);
        t1 += __shfl_xor_sync(0xffffffffu, t1, 2);
        if ((lane & 3) == 0) {
            float bb = b4[0];
            if (r0 < NN) { g_u4[r0] = u0 + bb; g_t4[r0] = t0; }
            if (r1 < NN) { g_u4[r1] = u1 + bb; g_t4[r1] = t1; }
        }
    }
}

// ---------------- layer 4 output: sigmoid(u4 + deginv * sum t4[nbrs]) ----------------
__global__ void k_out4(float* __restrict__ out) {
    int node = blockIdx.x * 8 + (threadIdx.x >> 5);
    if (node >= NN) return;
    int lane = threadIdx.x & 31;
    int start = g_rowptr[node];
    int cnt   = g_cnt[node];
    float acc = 0.f;
    for (int j = lane; j < cnt; j += 32) acc += g_t4[g_col[start + j]];
#pragma unroll
    for (int o = 16; o; o >>= 1) acc += __shfl_down_sync(0xffffffffu, acc, o);
    if (lane == 0) {
        float z = g_u4[node] + g_deginv[node] * acc;
        out[node] = 1.0f / (1.0f + expf(-z));
    }
}

// ---------------- launch ----------------
extern "C" void kernel_launch(void* const* d_in, const int* in_sizes, int n_in,
                              void* d_out, int out_size) {
    const float* x   = (const float*)d_in[0];
    const void*  ei  = d_in[1];
    const float* Ws1 = (const float*)d_in[2];
    const float* Wn1 = (const float*)d_in[3];
    const float* b1  = (const float*)d_in[4];
    const float* Ws2 = (const float*)d_in[5];
    const float* Wn2 = (const float*)d_in[6];
    const float* b2  = (const float*)d_in[7];
    const float* Ws3 = (const float*)d_in[8];
    const float* Wn3 = (const float*)d_in[9];
    const float* b3  = (const float*)d_in[10];
    const float* Ws4 = (const float*)d_in[11];
    const float* Wn4 = (const float*)d_in[12];
    const float* b4  = (const float*)d_in[13];
    float* out = (float*)d_out;

    static __half *pHa = nullptr, *pHb = nullptr, *pAg = nullptr;
    if (!pHa) {
        void* p;
        cudaGetSymbolAddress(&p, g_h16a);   pHa = (__half*)p;
        cudaGetSymbolAddress(&p, g_h16b);   pHb = (__half*)p;
        cudaGetSymbolAddress(&p, g_agg16);  pAg = (__half*)p;
        cudaFuncSetAttribute(k_gemm_hmma, cudaFuncAttributeMaxDynamicSharedMemorySize,
                             SMEM_HM);
    }

    const int gridN8 = (NN + 7) / 8;
    const int gridG  = (NN + 127) / 128;
    const int gridA  = (NN + 255) / 256;

    // CSR build (hist also converts x + weights; alloc replaces the scan)
    k_hist<<<GRID_E + 24, 256>>>(ei, x, pHa, Ws1, Wn1, Ws2, Wn2, Ws3, Wn3);
    k_alloc<<<gridA, 256>>>();
    k_fill<<<GRID_E, 256>>>(ei);

    // layer 1
    k_agg16<<<gridN8, 256>>>(pHa, pAg);
    k_gemm_hmma<<<gridG, 256, SMEM_HM>>>(pHa, pAg, 0, b1, pHb, Ws4, Wn4, b4, 0);
    // layer 2
    k_agg16<<<gridN8, 256>>>(pHb, pAg);
    k_gemm_hmma<<<gridG, 256, SMEM_HM>>>(pHb, pAg, 1, b2, pHa, Ws4, Wn4, b4, 0);
    // layer 3 (+ fused layer-4 linear; no layer-3 output store)
    k_agg16<<<gridN8, 256>>>(pHa, pAg);
    k_gemm_hmma<<<gridG, 256, SMEM_HM>>>(pHa, pAg, 2, b3, ((__half*)0), Ws4, Wn4, b4, 1);
    // layer 4 aggregation + sigmoid
    k_out4<<<gridN8, 256>>>(out);
}